// round 10
// baseline (speedup 1.0000x reference)
#include <cuda_runtime.h>
#include <math.h>
#include <stdint.h>

// ---------------- problem constants ----------------
#define B_SZ   4096
#define LATENT 512
#define D_     6
#define M_     16
#define K_     12      // knots
#define NB_    16
#define R_     128
#define HID_   256
#define KIN    518     // LATENT + D
#define NP_    368     // M*(1+NB+D)
#define NK_    192     // M*K

// output layout (tuple flattened in order)
#define OFF_LOGITS 0ull
#define OFF_MU     65536ull
#define OFF_SIG    50397184ull
#define OFF_MASK   100728832ull
#define OFF_BW     101515264ull

// ---------------- scratch (no allocs allowed) ----------------
__device__ float g_H [B_SZ * HID_];  // pre-LN hidden
__device__ float g_A [B_SZ * HID_];  // elu(LN(h))
__device__ float g_S [B_SZ * HID_];  // situation
__device__ float g_P [B_SZ * NP_];   // raw head
__device__ float g_Kc[B_SZ * NK_];   // knot logits

// =====================================================================
// GEMM core v3: C = A[BxK] @ W[KxN] + bias.
// BM=32, BN=128, KT=16, 64 threads, 8x8 microtile, double-buffered.
// Per k-step: 64B smem -> 64 FMA (1.0 FMA/B).
// =====================================================================
template<bool CONCAT>
__device__ __forceinline__ void g_loadA3(const float* __restrict__ A,
                                         const float* __restrict__ A2,
                                         int bm, int k0, int K, int tid,
                                         float ar[8]) {
#pragma unroll
    for (int i = 0; i < 2; i++) {
        const int idx = tid + i * 64;          // 0..127
        const int r   = bm + (idx >> 2);       // 32 rows
        const int k   = k0 + (idx & 3) * 4;
        float* dst = ar + i * 4;
        if (CONCAT) {
            if (k + 3 < LATENT) {
                float4 v = *(const float4*)(A + (size_t)r * LATENT + k);
                dst[0] = v.x; dst[1] = v.y; dst[2] = v.z; dst[3] = v.w;
            } else {
#pragma unroll
                for (int j = 0; j < 4; j++) {
                    int kk = k + j;
                    float v = 0.f;
                    if (kk < KIN)
                        v = (kk < LATENT) ? A [(size_t)r * LATENT + kk]
                                          : A2[(size_t)r * D_ + (kk - LATENT)];
                    dst[j] = v;
                }
            }
        } else {
            if (k + 3 < K) {
                float4 v = *(const float4*)(A + (size_t)r * K + k);
                dst[0] = v.x; dst[1] = v.y; dst[2] = v.z; dst[3] = v.w;
            } else {
#pragma unroll
                for (int j = 0; j < 4; j++)
                    dst[j] = (k + j < K) ? A[(size_t)r * K + k + j] : 0.f;
            }
        }
    }
}

__device__ __forceinline__ void g_loadW3(const float* __restrict__ W,
                                         int bn, int k0, int K, int N, int tid,
                                         float wr[32]) {
#pragma unroll
    for (int i = 0; i < 8; i++) {
        const int idx = tid + i * 64;          // 0..511
        const int kr  = idx >> 5;              // 0..15
        const int c0  = (idx & 31) * 4;        // 0..124
        const int k   = k0 + kr;
        float* dst = wr + i * 4;
        if (k < K && bn + c0 + 3 < N) {
            float4 v = *(const float4*)(W + (size_t)k * N + bn + c0);
            dst[0] = v.x; dst[1] = v.y; dst[2] = v.z; dst[3] = v.w;
        } else {
#pragma unroll
            for (int j = 0; j < 4; j++)
                dst[j] = (k < K && bn + c0 + j < N) ? W[(size_t)k * N + bn + c0 + j] : 0.f;
        }
    }
}

__device__ __forceinline__ void s_store3(float (*As)[32], float (*Ws)[128],
                                         int tid, const float ar[8], const float wr[32]) {
#pragma unroll
    for (int i = 0; i < 2; i++) {
        const int idx = tid + i * 64;
        const int r   = idx >> 2;
        const int kq  = (idx & 3) * 4;
#pragma unroll
        for (int j = 0; j < 4; j++) As[kq + j][r] = ar[i * 4 + j];
    }
#pragma unroll
    for (int i = 0; i < 8; i++) {
        const int idx = tid + i * 64;
        const int kr  = idx >> 5;
        const int c0  = (idx & 31) * 4;
        *(float4*)&Ws[kr][c0] = make_float4(wr[i*4], wr[i*4+1], wr[i*4+2], wr[i*4+3]);
    }
}

template<bool CONCAT>
__device__ __forceinline__ void gemm_core3(const float* __restrict__ A,
                                           const float* __restrict__ A2,
                                           const float* __restrict__ W,
                                           const float* __restrict__ bias,
                                           float* __restrict__ C,
                                           int K, int N, int bm, int bn) {
    __shared__ float As[2][16][32];    //  4 KB
    __shared__ float Ws[2][16][128];   // 16 KB

    const int tid = threadIdx.x;       // 64
    const int tx  = tid & 15;          // col group (x8)
    const int ty  = tid >> 4;          // row group (x8), 0..3

    float acc[8][8];
#pragma unroll
    for (int i = 0; i < 8; i++)
#pragma unroll
        for (int j = 0; j < 8; j++) acc[i][j] = 0.f;

    float ar[8], wr[32];
    g_loadA3<CONCAT>(A, A2, bm, 0, K, tid, ar);
    g_loadW3(W, bn, 0, K, N, tid, wr);
    s_store3(As[0], Ws[0], tid, ar, wr);
    __syncthreads();

    const int nT = (K + 15) >> 4;
    for (int t = 0; t < nT; t++) {
        const int cur = t & 1;
        const bool more = (t + 1 < nT);
        if (more) {
            g_loadA3<CONCAT>(A, A2, bm, (t + 1) * 16, K, tid, ar);
            g_loadW3(W, bn, (t + 1) * 16, K, N, tid, wr);
        }
#pragma unroll
        for (int k = 0; k < 16; k++) {
            float av[8], bv[8];
            float4 t0 = *(const float4*)&As[cur][k][ty * 8];
            float4 t1 = *(const float4*)&As[cur][k][ty * 8 + 4];
            av[0]=t0.x; av[1]=t0.y; av[2]=t0.z; av[3]=t0.w;
            av[4]=t1.x; av[5]=t1.y; av[6]=t1.z; av[7]=t1.w;
            float4 u0 = *(const float4*)&Ws[cur][k][tx * 8];
            float4 u1 = *(const float4*)&Ws[cur][k][tx * 8 + 4];
            bv[0]=u0.x; bv[1]=u0.y; bv[2]=u0.z; bv[3]=u0.w;
            bv[4]=u1.x; bv[5]=u1.y; bv[6]=u1.z; bv[7]=u1.w;
#pragma unroll
            for (int i = 0; i < 8; i++)
#pragma unroll
                for (int j = 0; j < 8; j++)
                    acc[i][j] += av[i] * bv[j];
        }
        if (more) {
            s_store3(As[cur ^ 1], Ws[cur ^ 1], tid, ar, wr);
            __syncthreads();
        }
    }

    const int c = bn + tx * 8;
    if (c + 7 < N) {
        float4 b0 = *(const float4*)(bias + c);
        float4 b1 = *(const float4*)(bias + c + 4);
#pragma unroll
        for (int i = 0; i < 8; i++) {
            int row = bm + ty * 8 + i;
            float4 o0 = make_float4(acc[i][0] + b0.x, acc[i][1] + b0.y,
                                    acc[i][2] + b0.z, acc[i][3] + b0.w);
            float4 o1 = make_float4(acc[i][4] + b1.x, acc[i][5] + b1.y,
                                    acc[i][6] + b1.z, acc[i][7] + b1.w);
            *(float4*)(C + (size_t)row * N + c)     = o0;
            *(float4*)(C + (size_t)row * N + c + 4) = o1;
        }
    } else {
#pragma unroll
        for (int i = 0; i < 8; i++) {
            int row = bm + ty * 8 + i;
#pragma unroll
            for (int j = 0; j < 8; j++)
                if (c + j < N) C[(size_t)row * N + c + j] = acc[i][j] + bias[c + j];
        }
    }
}

template<bool CONCAT>
__global__ void __launch_bounds__(64)
gemm_db_kernel(const float* __restrict__ A,
               const float* __restrict__ A2,
               const float* __restrict__ W,
               const float* __restrict__ bias,
               float* __restrict__ C,
               int K, int N) {
    gemm_core3<CONCAT>(A, A2, W, bias, C, K, N, blockIdx.y * 32, blockIdx.x * 128);
}

// Fused head GEMMs: Wp col tiles 0..2 (N=368), Wk tiles 3..4 (N=192).
__global__ void __launch_bounds__(64)
gemm_heads_kernel(const float* __restrict__ S,
                  const float* __restrict__ Wp, const float* __restrict__ bp,
                  const float* __restrict__ Wk, const float* __restrict__ bk) {
    const int ct = blockIdx.x;
    const int bm = blockIdx.y * 32;
    if (ct < 3)
        gemm_core3<false>(S, nullptr, Wp, bp, g_P,  HID_, NP_, bm, ct * 128);
    else
        gemm_core3<false>(S, nullptr, Wk, bk, g_Kc, HID_, NK_, bm, (ct - 3) * 128);
}

// ---------------- LayerNorm + elu ----------------
__global__ void ln_elu_kernel(const float* __restrict__ g,
                              const float* __restrict__ bb) {
    const int b = blockIdx.x;
    const int t = threadIdx.x;   // 256
    float x = g_H[(size_t)b * HID_ + t];
    float v = x, v2 = x * x;
#pragma unroll
    for (int o = 16; o > 0; o >>= 1) {
        v  += __shfl_xor_sync(0xffffffffu, v,  o);
        v2 += __shfl_xor_sync(0xffffffffu, v2, o);
    }
    __shared__ float s1[8], s2[8];
    int wid = t >> 5, lane = t & 31;
    if (lane == 0) { s1[wid] = v; s2[wid] = v2; }
    __syncthreads();
    float tot = 0.f, tot2 = 0.f;
#pragma unroll
    for (int i = 0; i < 8; i++) { tot += s1[i]; tot2 += s2[i]; }
    float mu  = tot * (1.f / 256.f);
    float var = tot2 * (1.f / 256.f) - mu * mu;
    float y = (x - mu) * rsqrtf(var + 1e-5f) * g[t] + bb[t];
    g_A[(size_t)b * HID_ + t] = (y > 0.f) ? y : expm1f(y);
}

// =====================================================================
// Fused epilogue: heads + knot einsum + fixups + spline.
// One block per batch row, one warp per mixture; staged coalesced stores.
// =====================================================================
__global__ void __launch_bounds__(512)
epilogue_kernel(const float* __restrict__ prev_vel,
                const float* __restrict__ intent,
                const float* __restrict__ basis,
                float* __restrict__ out) {
    const int b    = blockIdx.x;
    const int tid  = threadIdx.x;     // 512
    const int m    = tid >> 5;        // warp id = mixture index
    const int lane = tid & 31;
    const int bmix = b * M_ + m;

    __shared__ float basis_s[NB_ * K_ * D_];   // 1152 floats
    __shared__ float pv_s[D_], it_s[D_];
    __shared__ float bw_s[M_][NB_];
    __shared__ float sig_s[M_][D_ + 2];
    __shared__ __align__(8) float knb[M_][K_ * D_];
    __shared__ int   cidx_s[M_][K_];
    __shared__ float stage[M_][384];           // 24 KB: half of mu per warp

    for (int i = tid; i < NB_ * K_ * D_; i += 512) basis_s[i] = basis[i];
    if (tid == 0) {
        float n2 = 0.f, pv[D_];
#pragma unroll
        for (int d = 0; d < D_; d++) { pv[d] = prev_vel[(size_t)b * D_ + d]; n2 += pv[d] * pv[d]; }
        float inv = 1.f / (sqrtf(n2) + 1e-6f);
#pragma unroll
        for (int d = 0; d < D_; d++) {
            pv_s[d] = pv[d] * inv;
            it_s[d] = intent[(size_t)b * D_ + d];
        }
    }
    __syncthreads();

    // ---- heads (lanes 0..22) ----
    float r = 0.f;
    if (lane < 23) r = g_P[(size_t)b * NP_ + m * 23 + lane];
    if (lane == 0) {
        out[OFF_LOGITS + (size_t)bmix] = r;
    } else if (lane <= NB_) {
        float v = tanhf(r);
        bw_s[m][lane - 1] = v;
        out[OFF_BW + (size_t)bmix * NB_ + (lane - 1)] = v;
    } else if (lane < 23) {
        sig_s[m][lane - 1 - NB_] = expf(r) + 0.1f;
    }
    // ---- knot mask (lanes 0..11) ----
    if (lane < K_) cidx_s[m][lane] = 0;
    float mv = 0.f;
    if (lane < K_) {
        float kv = g_Kc[(size_t)b * NK_ + m * K_ + lane];
        float sg = 1.f / (1.f + expf(-kv));
        mv = (lane == 0 || lane == K_ - 1) ? 1.0f : sg;
        out[OFF_MASK + (size_t)bmix * K_ + lane] = mv;
    }
    unsigned bal = __ballot_sync(0xffffffffu, (lane < K_) && (mv > 0.5f));
    if ((lane < K_) && (mv > 0.5f)) {
        int pos = __popc(bal & ((1u << lane) - 1u));
        cidx_s[m][pos] = lane;
    }
    __syncwarp();

    // ---- knots = tanh(raw) @ basis, knot0 subtracted ----
    for (int i = lane; i < K_ * D_; i += 32) {
        int d = i % D_;
        float acc = 0.f, acc0 = 0.f;
#pragma unroll
        for (int n = 0; n < NB_; n++) {
            float bwv = bw_s[m][n];
            acc  += bwv * basis_s[n * (K_ * D_) + i];
            acc0 += bwv * basis_s[n * (K_ * D_) + d];
        }
        knb[m][i] = acc - acc0;
    }
    __syncwarp();

    // ---- knot-1 alignment + last-knot intent shift (lane 0) ----
    if (lane == 0) {
        float n2 = 0.f, fs[D_];
#pragma unroll
        for (int d = 0; d < D_; d++) { fs[d] = knb[m][D_ + d]; n2 += fs[d] * fs[d]; }
        float mag = sqrtf(n2);
        float invm = 1.f / (mag + 1e-6f);
        float al[D_]; float an2 = 0.f;
#pragma unroll
        for (int d = 0; d < D_; d++) {
            float fn = fs[d] * invm;
            al[d] = 0.8f * pv_s[d] + 0.2f * fn;
            an2 += al[d] * al[d];
        }
        float inva = 1.f / (sqrtf(an2) + 1e-6f);
#pragma unroll
        for (int d = 0; d < D_; d++) knb[m][D_ + d] = al[d] * inva * mag;
#pragma unroll
        for (int d = 0; d < D_; d++) knb[m][(K_ - 1) * D_ + d] += 0.5f * it_s[d];
    }
    __syncwarp();

    // ---- Catmull-Rom spline ----
    const int count = __popc(bal);
    const float c1 = (1.0f / 127.0f) * (float)(count - 1);
    const size_t obase = (size_t)bmix * (R_ * D_);   // 768 floats per (b,m)

#pragma unroll
    for (int half = 0; half < 2; half++) {
        const int idx = half * 32 + lane;     // owns r = 2*idx, 2*idx+1
        float va[12];
#pragma unroll
        for (int h = 0; h < 2; h++) {
            const int rr = idx * 2 + h;
            float xs = (float)rr * c1;
            int j = (int)xs;                  // xs >= 0 -> trunc == floor
            if (j > count - 2) j = count - 2;
            if (j < 0) j = 0;
            float u  = xs - (float)j;
            float u2 = u * u, u3 = u2 * u;
            float w0 = 0.5f * (-u3 + 2.f * u2 - u);
            float w1 = 0.5f * (3.f * u3 - 5.f * u2 + 2.f);
            float w2 = 0.5f * (-3.f * u3 + 4.f * u2 + u);
            float w3 = 0.5f * (u3 - u2);
            int i0 = cidx_s[m][(j - 1 > 0) ? j - 1 : 0];
            int i1 = cidx_s[m][j];
            int i2 = cidx_s[m][j + 1];
            int i3 = cidx_s[m][(j + 2 < count - 1) ? j + 2 : count - 1];
            const float* k0p = &knb[m][i0 * D_];
            const float* k1p = &knb[m][i1 * D_];
            const float* k2p = &knb[m][i2 * D_];
            const float* k3p = &knb[m][i3 * D_];
#pragma unroll
            for (int d2 = 0; d2 < 3; d2++) {
                float2 q0 = *(const float2*)(k0p + 2 * d2);
                float2 q1 = *(const float2*)(k1p + 2 * d2);
                float2 q2 = *(const float2*)(k2p + 2 * d2);
                float2 q3 = *(const float2*)(k3p + 2 * d2);
                va[h * D_ + 2 * d2]     = w0 * q0.x + w1 * q1.x + w2 * q2.x + w3 * q3.x;
                va[h * D_ + 2 * d2 + 1] = w0 * q0.y + w1 * q1.y + w2 * q2.y + w3 * q3.y;
            }
        }
        float4* st = (float4*)&stage[m][lane * 12];
        st[0] = make_float4(va[0], va[1], va[2],  va[3]);
        st[1] = make_float4(va[4], va[5], va[6],  va[7]);
        st[2] = make_float4(va[8], va[9], va[10], va[11]);
        __syncwarp();
        float* dst = out + OFF_MU + obase + (size_t)half * 384;
#pragma unroll
        for (int q = 0; q < 3; q++) {
            int p = lane + 32 * q;
            float4 v = *(float4*)&stage[m][p * 4];
            *(float4*)(dst + (size_t)p * 4) = v;
        }
        __syncwarp();
    }

    // ---- sigma: warp-uniform float4 patterns, direct coalesced stores ----
    {
        const float s0 = sig_s[m][0], s1v = sig_s[m][1], s2v = sig_s[m][2];
        const float s3 = sig_s[m][3], s4v = sig_s[m][4], s5v = sig_s[m][5];
        const float4 pat[3] = {
            make_float4(s0,  s1v, s2v, s3),
            make_float4(s4v, s5v, s0,  s1v),
            make_float4(s2v, s3,  s4v, s5v)
        };
        float* dst = out + OFF_SIG + obase;
#pragma unroll
        for (int q = 0; q < 6; q++) {
            int p = lane + 32 * q;
            int sel = p - (p / 3) * 3;
            *(float4*)(dst + (size_t)p * 4) = pat[sel];
        }
    }
}

// ---------------- launcher ----------------
extern "C" void kernel_launch(void* const* d_in, const int* in_sizes, int n_in,
                              void* d_out, int out_size) {
    (void)in_sizes; (void)n_in; (void)out_size;
    const float* ls     = (const float*)d_in[0];
    const float* intent = (const float*)d_in[1];
    const float* pvel   = (const float*)d_in[2];
    const float* W1     = (const float*)d_in[3];
    const float* b1     = (const float*)d_in[4];
    const float* lng    = (const float*)d_in[5];
    const float* lnb    = (const float*)d_in[6];
    const float* W2     = (const float*)d_in[7];
    const float* b2     = (const float*)d_in[8];
    const float* Wp     = (const float*)d_in[9];
    const float* bp     = (const float*)d_in[10];
    const float* Wk     = (const float*)d_in[11];
    const float* bk     = (const float*)d_in[12];
    const float* basis  = (const float*)d_in[13];
    float* out = (float*)d_out;

    float *pH, *pA, *pS;
    cudaGetSymbolAddress((void**)&pH, g_H);
    cudaGetSymbolAddress((void**)&pA, g_A);
    cudaGetSymbolAddress((void**)&pS, g_S);

    // 1) H = concat(ls, intent) @ W1 + b1   (grid 2 x 128 = 256 blocks)
    gemm_db_kernel<true><<<dim3(HID_ / 128, B_SZ / 32), 64>>>(ls, intent, W1, b1, pH, KIN, HID_);
    // 2) A = elu(LN(H))
    ln_elu_kernel<<<B_SZ, 256>>>(lng, lnb);
    // 3) S = A @ W2 + b2
    gemm_db_kernel<false><<<dim3(HID_ / 128, B_SZ / 32), 64>>>(pA, nullptr, W2, b2, pS, HID_, HID_);
    // 4+5) P = S @ Wp + bp  and  Kc = S @ Wk + bk   (5 col tiles x 128 rows)
    gemm_heads_kernel<<<dim3(5, B_SZ / 32), 64>>>(pS, Wp, bp, Wk, bk);
    // 6) fused epilogue (heads + knots + spline + all outputs)
    epilogue_kernel<<<B_SZ, 512>>>(pvel, intent, basis, out);
}